// round 14
// baseline (speedup 1.0000x reference)
#include <cuda_runtime.h>
#include <cstdint>

#define COLS 8192
#define COLS4 2048
#define ROWS 1024
#define SCALE 0.75f
#define HALF 4096
#define NSLOT 3
// Padded smem: physical index p(j) = j + (j>>3); 2048 float4 -> 2304 float4.
#define WS_PHYS 2304

// Scratch (no allocation allowed). 32B-aligned for LDG.256.
__device__ __align__(32) float g_wtotal[COLS];

// LDG.256 + evict_last (x stream: L2-resident across graph replays).
__device__ __forceinline__ void ldg256_el(const float* p, float4& a, float4& b) {
    unsigned r0, r1, r2, r3, r4, r5, r6, r7;
    asm volatile("ld.global.nc.L2::evict_last.v8.b32 {%0,%1,%2,%3,%4,%5,%6,%7}, [%8];"
        : "=r"(r0), "=r"(r1), "=r"(r2), "=r"(r3),
          "=r"(r4), "=r"(r5), "=r"(r6), "=r"(r7)
        : "l"(p));
    a.x = __uint_as_float(r0); a.y = __uint_as_float(r1);
    a.z = __uint_as_float(r2); a.w = __uint_as_float(r3);
    b.x = __uint_as_float(r4); b.y = __uint_as_float(r5);
    b.z = __uint_as_float(r6); b.w = __uint_as_float(r7);
}

// ---------------- Kernel 1: w_total[c] = sum_g wsums[g][c] ----------------
__global__ __launch_bounds__(256) void reduce_w_kernel(const float* __restrict__ wsums) {
    const int lcol  = threadIdx.x & 31;
    const int chunk = threadIdx.x >> 5;               // 0..7, 4 groups each
    const int c4    = blockIdx.x * 32 + lcol;

    const float4* __restrict__ w4 = reinterpret_cast<const float4*>(wsums);
    float4 s = make_float4(0.f, 0.f, 0.f, 0.f);
#pragma unroll
    for (int g = 0; g < 4; ++g) {
        float4 v = w4[(size_t)(chunk * 4 + g) * COLS4 + c4];
        s.x += v.x; s.y += v.y; s.z += v.z; s.w += v.w;
    }

    __shared__ float4 sm[8][32];
    sm[chunk][lcol] = s;
    __syncthreads();

    if (threadIdx.x < 32) {
        float4 r = make_float4(0.f, 0.f, 0.f, 0.f);
#pragma unroll
        for (int c = 0; c < 8; ++c) {
            float4 v = sm[c][threadIdx.x];
            r.x += v.x; r.y += v.y; r.z += v.z; r.w += v.w;
        }
        reinterpret_cast<float4*>(g_wtotal)[c4] = r;
    }
}

// ---------------- Kernel 2: half-row warps, w in padded SMEM ----------------
// Grid 256 x 256 thr (8 warps). Warp wid owns half (wid&1) of row
// bid*4+(wid>>1): 16-iteration LDG.256 stream with a 3-slot rotation.
// w lives in SMEM (loaded once per block), padded p(j)=j+(j>>3) so the
// stride-32B LDS.128 pattern is bank-conflict-free. Reg cap 64 -> 4 blocks/SM.
__global__ __launch_bounds__(256, 4) void dot_smem_kernel(const float* __restrict__ x,
                                                          float* __restrict__ out) {
    __shared__ float4 ws[WS_PHYS];        // 36,864 B
    __shared__ float red[8];

    const int t   = threadIdx.x;
    const int wid = t >> 5;
    const int lid = t & 31;
    const int row  = blockIdx.x * 4 + (wid >> 1);
    const int half = wid & 1;

    const float* __restrict__ xr = x + (size_t)row * COLS + half * HALF + lid * 8;

    // Prefetch x slots 0..2 before touching w (covers w smem fill latency).
    float4 pa[NSLOT][2];
#pragma unroll
    for (int i = 0; i < NSLOT; ++i)
        ldg256_el(xr + i * 256, pa[i][0], pa[i][1]);

    // Cooperative w -> padded smem: thread handles j = t, t+256, ... (8 float4).
    {
        const float4* __restrict__ w4 = reinterpret_cast<const float4*>(g_wtotal);
#pragma unroll
        for (int m = 0; m < 8; ++m) {
            const int j = m * 256 + t;
            ws[j + (j >> 3)] = w4[j];
        }
    }
    __syncthreads();

    const int jbase = half * 1024 + lid * 2;   // logical float4 index, this lane

    float p0 = 0.f, p1 = 0.f, p2 = 0.f, p3 = 0.f;
#pragma unroll
    for (int i = 0; i < 16; ++i) {
        const int slot = i % NSLOT;
        const float4 a0 = pa[slot][0], a1 = pa[slot][1];
        if (i + NSLOT < 16)
            ldg256_el(xr + (i + NSLOT) * 256, pa[slot][0], pa[slot][1]);

        const int j = jbase + i * 64;
        const int pj = j + (j >> 3);
        const float4 w0 = ws[pj];
        const float4 w1 = ws[pj + 1];

        p0 = fmaf(a0.x, w0.x, p0); p1 = fmaf(a0.y, w0.y, p1);
        p2 = fmaf(a0.z, w0.z, p2); p3 = fmaf(a0.w, w0.w, p3);
        p0 = fmaf(a1.x, w1.x, p0); p1 = fmaf(a1.y, w1.y, p1);
        p2 = fmaf(a1.z, w1.z, p2); p3 = fmaf(a1.w, w1.w, p3);
    }
    float s = (p0 + p1) + (p2 + p3);

    // Warp reduce.
#pragma unroll
    for (int o = 16; o > 0; o >>= 1)
        s += __shfl_xor_sync(0xFFFFFFFFu, s, o);

    if (lid == 0) red[wid] = s;
    __syncthreads();

    if (t < 4)
        out[blockIdx.x * 4 + t] = SCALE * (red[2 * t] + red[2 * t + 1]);
}

extern "C" void kernel_launch(void* const* d_in, const int* in_sizes, int n_in,
                              void* d_out, int out_size) {
    const float* x     = (const float*)d_in[0];  // [1024, 8192] f32
    const float* wsums = (const float*)d_in[1];  // [32, 8192] f32
    float* out         = (float*)d_out;          // [1024, 1] f32

    reduce_w_kernel<<<COLS4 / 32, 256>>>(wsums);
    dot_smem_kernel<<<ROWS / 4, 256>>>(x, out);
}

// round 15
// speedup vs baseline: 1.2294x; 1.2294x over previous
#include <cuda_runtime.h>
#include <cstdint>

#define COLS 8192
#define COLS4 2048
#define ROWS 1024
#define SCALE 0.75f
#define HALF 4096             // floats per half-row

// Scratch (no allocation allowed). 32B-aligned for LDG.256.
__device__ __align__(32) float g_wtotal[COLS];

// LDG.256 + evict_last (x stream: L2-resident across graph replays).
__device__ __forceinline__ void ldg256_el(const float* p, float4& a, float4& b) {
    unsigned r0, r1, r2, r3, r4, r5, r6, r7;
    asm volatile("ld.global.nc.L2::evict_last.v8.b32 {%0,%1,%2,%3,%4,%5,%6,%7}, [%8];"
        : "=r"(r0), "=r"(r1), "=r"(r2), "=r"(r3),
          "=r"(r4), "=r"(r5), "=r"(r6), "=r"(r7)
        : "l"(p));
    a.x = __uint_as_float(r0); a.y = __uint_as_float(r1);
    a.z = __uint_as_float(r2); a.w = __uint_as_float(r3);
    b.x = __uint_as_float(r4); b.y = __uint_as_float(r5);
    b.z = __uint_as_float(r6); b.w = __uint_as_float(r7);
}
// Plain LDG.256 (w: L1/L2-hot).
__device__ __forceinline__ void ldg256(const float* p, float4& a, float4& b) {
    unsigned r0, r1, r2, r3, r4, r5, r6, r7;
    asm volatile("ld.global.nc.v8.b32 {%0,%1,%2,%3,%4,%5,%6,%7}, [%8];"
        : "=r"(r0), "=r"(r1), "=r"(r2), "=r"(r3),
          "=r"(r4), "=r"(r5), "=r"(r6), "=r"(r7)
        : "l"(p));
    a.x = __uint_as_float(r0); a.y = __uint_as_float(r1);
    a.z = __uint_as_float(r2); a.w = __uint_as_float(r3);
    b.x = __uint_as_float(r4); b.y = __uint_as_float(r5);
    b.z = __uint_as_float(r6); b.w = __uint_as_float(r7);
}

// ---------------- Kernel 1: w_total[c] = sum_g wsums[g][c] ----------------
__global__ __launch_bounds__(256) void reduce_w_kernel(const float* __restrict__ wsums) {
    const int lcol  = threadIdx.x & 31;
    const int chunk = threadIdx.x >> 5;               // 0..7, 4 groups each
    const int c4    = blockIdx.x * 32 + lcol;

    const float4* __restrict__ w4 = reinterpret_cast<const float4*>(wsums);
    float4 s = make_float4(0.f, 0.f, 0.f, 0.f);
#pragma unroll
    for (int g = 0; g < 4; ++g) {
        float4 v = w4[(size_t)(chunk * 4 + g) * COLS4 + c4];
        s.x += v.x; s.y += v.y; s.z += v.z; s.w += v.w;
    }

    __shared__ float4 sm[8][32];
    sm[chunk][lcol] = s;
    __syncthreads();

    if (threadIdx.x < 32) {
        float4 r = make_float4(0.f, 0.f, 0.f, 0.f);
#pragma unroll
        for (int c = 0; c < 8; ++c) {
            float4 v = sm[c][threadIdx.x];
            r.x += v.x; r.y += v.y; r.z += v.z; r.w += v.w;
        }
        reinterpret_cast<float4*>(g_wtotal)[c4] = r;
    }
}

// ---------------- Kernel 2: R11 body + PDL prefetch ----------------
// Grid 256 x 256 thr (8 warps). Warp wid owns half (wid&1) of row
// bid*4+(wid>>1): 16-iteration LDG.256 stream, 2-slot rotation. The first
// two x iterations are issued BEFORE cudaGridDependencySynchronize(), so
// reduce_w's tail drains under the x prefetch instead of serializing.
__global__ __launch_bounds__(256, 3) void dot_warp_kernel(const float* __restrict__ x,
                                                          float* __restrict__ out) {
    const int t   = threadIdx.x;
    const int wid = t >> 5;
    const int lid = t & 31;
    const int row  = blockIdx.x * 4 + (wid >> 1);
    const int half = wid & 1;

    const float* __restrict__ xr = x + (size_t)row * COLS + half * HALF + lid * 8;
    const float* __restrict__ wr = g_wtotal + half * HALF + lid * 8;

    // Prefetch x iterations 0,1 (no w dependency) before the PDL wait.
    float4 pa[2][2];
    ldg256_el(xr + 0 * 256, pa[0][0], pa[0][1]);
    ldg256_el(xr + 1 * 256, pa[1][0], pa[1][1]);

    cudaGridDependencySynchronize();     // wait for reduce_w's g_wtotal writes

    float p0 = 0.f, p1 = 0.f, p2 = 0.f, p3 = 0.f;
#pragma unroll
    for (int i = 0; i < 16; ++i) {
        const int slot = i & 1;
        float4 w0, w1;
        ldg256(wr + i * 256, w0, w1);
        const float4 a0 = pa[slot][0], a1 = pa[slot][1];
        if (i + 2 < 16)
            ldg256_el(xr + (i + 2) * 256, pa[slot][0], pa[slot][1]);
        p0 = fmaf(a0.x, w0.x, p0); p1 = fmaf(a0.y, w0.y, p1);
        p2 = fmaf(a0.z, w0.z, p2); p3 = fmaf(a0.w, w0.w, p3);
        p0 = fmaf(a1.x, w1.x, p0); p1 = fmaf(a1.y, w1.y, p1);
        p2 = fmaf(a1.z, w1.z, p2); p3 = fmaf(a1.w, w1.w, p3);
    }
    float s = (p0 + p1) + (p2 + p3);

    // Warp reduce.
#pragma unroll
    for (int o = 16; o > 0; o >>= 1)
        s += __shfl_xor_sync(0xFFFFFFFFu, s, o);

    __shared__ float red[8];
    if (lid == 0) red[wid] = s;
    __syncthreads();

    if (t < 4)
        out[blockIdx.x * 4 + t] = SCALE * (red[2 * t] + red[2 * t + 1]);
}

extern "C" void kernel_launch(void* const* d_in, const int* in_sizes, int n_in,
                              void* d_out, int out_size) {
    const float* x     = (const float*)d_in[0];  // [1024, 8192] f32
    const float* wsums = (const float*)d_in[1];  // [32, 8192] f32
    float* out         = (float*)d_out;          // [1024, 1] f32

    reduce_w_kernel<<<COLS4 / 32, 256>>>(wsums);

    // PDL: dot's prologue (x prefetch) runs while reduce_w drains.
    cudaLaunchConfig_t cfg = {};
    cfg.gridDim  = dim3(ROWS / 4, 1, 1);
    cfg.blockDim = dim3(256, 1, 1);
    cfg.dynamicSmemBytes = 0;
    cfg.stream = 0;
    cudaLaunchAttribute at[1];
    at[0].id = cudaLaunchAttributeProgrammaticStreamSerialization;
    at[0].val.programmaticStreamSerializationAllowed = 1;
    cfg.attrs = at;
    cfg.numAttrs = 1;
    cudaLaunchKernelEx(&cfg, dot_warp_kernel, x, (float*)d_out);
}